// round 15
// baseline (speedup 1.0000x reference)
#include <cuda_runtime.h>
#include <math.h>
#include <stdint.h>

// Problem constants
#define Bq   4
#define Tq   2048
#define Eq   1024
#define Hq   16
#define Dq   64
#define BHq  (Bq*Hq)

// Scratch (alloc-free rule: static __device__ arrays).
__device__ uint16_t g_Qb [(size_t)BHq * Tq * Dq];  // bf16, d pair-permuted, pre-scaled
__device__ uint16_t g_Kb [(size_t)BHq * Tq * Dq];  // bf16, d pair-permuted
__device__ float    g_V  [(size_t)BHq * Tq * Dq];  // fp32 row-major (exact residual)
__device__ uint16_t g_Vtb[(size_t)BHq * Dq * Tq];  // bf16, transposed, t pair-permuted

#define SCALE_LOG2E 0.18033688011112042f   // 0.125 * log2(e)

// ---- bf16 pack: {lo, hi} -> bf16x2 in one u32 ----
__device__ __forceinline__ uint32_t bf2(float lo, float hi) {
    uint32_t r;
    asm("cvt.rn.bf16x2.f32 %0, %1, %2;" : "=r"(r) : "f"(hi), "f"(lo));
    return r;
}

// split a float2 into bf16x2 hi part and bf16x2 residual (lo) part.
__device__ __forceinline__ void split2(float2 p, uint32_t& hi, uint32_t& lo) {
    hi = bf2(p.x, p.y);
    float h0 = __uint_as_float(hi << 16);
    float h1 = __uint_as_float(hi & 0xffff0000u);
    lo = bf2(p.x - h0, p.y - h1);
}

// ---- warp-level bf16 MMA: D(16x8,f32) += A(16x16,bf16) * B(16x8,bf16) ----
__device__ __forceinline__ void mma_bf16(float c[4], const uint32_t a[4],
                                         uint32_t b0, uint32_t b1) {
    asm volatile(
        "mma.sync.aligned.m16n8k16.row.col.f32.bf16.bf16.f32 "
        "{%0,%1,%2,%3}, {%4,%5,%6,%7}, {%8,%9}, {%0,%1,%2,%3};"
        : "+f"(c[0]), "+f"(c[1]), "+f"(c[2]), "+f"(c[3])
        : "r"(a[0]), "r"(a[1]), "r"(a[2]), "r"(a[3]), "r"(b0), "r"(b1));
}

__device__ __forceinline__ float ex2f(float x) {
    float r; asm("ex2.approx.f32 %0, %1;" : "=f"(r) : "f"(x)); return r;
}
__device__ __forceinline__ uint32_t smem_u32(const void* p) {
    uint32_t a;
    asm("{ .reg .u64 t; cvta.to.shared.u64 t, %1; cvt.u32.u64 %0, t; }" : "=r"(a) : "l"(p));
    return a;
}

#define CP_ASYNC16(dst_u32, src_ptr) \
    asm volatile("cp.async.ca.shared.global [%0], [%1], 16;" :: "r"(dst_u32), "l"(src_ptr) : "memory")
#define CP_COMMIT() asm volatile("cp.async.commit_group;" ::: "memory")
#define CP_WAIT(n)  asm volatile("cp.async.wait_group %0;" :: "n"(n) : "memory")

// ============================================================================
// Kernel 1: tensor-core projections with error-compensated bf16 (R9 verbatim
// — proven 62us). Single uniform m-loop: C = xh*Wh + xl*Wh + xh*Wl.
// ============================================================================
#define PT 66   // smem transpose pitch (floats)

__global__ void __launch_bounds__(128) proj_kernel(
    const float* __restrict__ x,
    const float* __restrict__ Wq,
    const float* __restrict__ Wk,
    const float* __restrict__ Wv)
{
    __shared__ float sVt[128 * PT];

    const int tid  = threadIdx.x;
    const int lane = tid & 31;
    const int wid  = tid >> 5;
    const int lg   = lane >> 2;
    const int lt   = lane & 3;

    const int bh = blockIdx.y;
    const int b  = bh >> 4;
    const int h  = bh & 15;
    const int t0 = blockIdx.x * 128;
    const int wq = t0 + wid * 32;

    // ---- load x tile as hi/lo bf16 A-fragments ----
    uint32_t aXh[2][4][4], aXl[2][4][4];
    #pragma unroll
    for (int mt = 0; mt < 2; ++mt) {
        #pragma unroll
        for (int kj = 0; kj < 4; ++kj) {
            const int r0 = wq + mt * 16 + lg;
            const float* p = x + ((size_t)(b * Tq + r0)) * Eq + h * Dq + kj * 16 + 2 * lt;
            float2 lo0 = *(const float2*)(p);
            float2 hi0 = *(const float2*)(p + 8);
            const float* q = p + (size_t)8 * Eq;
            float2 lo1 = *(const float2*)(q);
            float2 hi1 = *(const float2*)(q + 8);
            split2(lo0, aXh[mt][kj][0], aXl[mt][kj][0]);
            split2(lo1, aXh[mt][kj][1], aXl[mt][kj][1]);
            split2(hi0, aXh[mt][kj][2], aXl[mt][kj][2]);
            split2(hi1, aXh[mt][kj][3], aXl[mt][kj][3]);
        }
    }

    #pragma unroll 1
    for (int m = 0; m < 3; ++m) {
        const float* W = (m == 0) ? Wq : ((m == 1) ? Wk : Wv);

        float c[2][8][4];
        #pragma unroll
        for (int mt = 0; mt < 2; ++mt)
            #pragma unroll
            for (int nt = 0; nt < 8; ++nt)
                #pragma unroll
                for (int e = 0; e < 4; ++e) c[mt][nt][e] = 0.f;

        #pragma unroll
        for (int kj = 0; kj < 4; ++kj) {
            #pragma unroll
            for (int nt = 0; nt < 8; ++nt) {
                const float* wp = W + (size_t)(nt * 8 + lg) * 64 + kj * 16 + 2 * lt;
                uint32_t wh0, wl0, wh1, wl1;
                split2(*(const float2*)(wp),     wh0, wl0);
                split2(*(const float2*)(wp + 8), wh1, wl1);
                #pragma unroll
                for (int mt = 0; mt < 2; ++mt) {
                    mma_bf16(c[mt][nt], aXh[mt][kj], wh0, wh1);
                    mma_bf16(c[mt][nt], aXl[mt][kj], wh0, wh1);
                    mma_bf16(c[mt][nt], aXh[mt][kj], wl0, wl1);
                }
            }
        }

        if (m < 2) {
            uint16_t* g = (m == 0 ? g_Qb : g_Kb);
            const float s = (m == 0) ? SCALE_LOG2E : 1.0f;
            #pragma unroll
            for (int mt = 0; mt < 2; ++mt) {
                const int t = wq + mt * 16 + lg;
                uint16_t* r0 = g + ((size_t)bh * Tq + t) * Dq;
                uint16_t* r1 = r0 + (size_t)8 * Dq;
                #pragma unroll
                for (int nt = 0; nt < 8; ++nt) {
                    const int pos = 16 * (nt >> 1) + 4 * lt + 2 * (nt & 1);
                    *(uint32_t*)(r0 + pos) = bf2(c[mt][nt][0] * s, c[mt][nt][1] * s);
                    *(uint32_t*)(r1 + pos) = bf2(c[mt][nt][2] * s, c[mt][nt][3] * s);
                }
            }
        } else {
            #pragma unroll
            for (int mt = 0; mt < 2; ++mt) {
                const int t    = wq + mt * 16 + lg;
                const int tloc = wid * 32 + mt * 16 + lg;
                float* r0 = g_V + ((size_t)bh * Tq + t) * Dq;
                float* r1 = r0 + (size_t)8 * Dq;
                #pragma unroll
                for (int nt = 0; nt < 8; ++nt) {
                    const int col = nt * 8 + 2 * lt;
                    *(float2*)(r0 + col) = make_float2(c[mt][nt][0], c[mt][nt][1]);
                    *(float2*)(r1 + col) = make_float2(c[mt][nt][2], c[mt][nt][3]);
                    *(float2*)(sVt + tloc * PT + col)       = make_float2(c[mt][nt][0], c[mt][nt][1]);
                    *(float2*)(sVt + (tloc + 8) * PT + col) = make_float2(c[mt][nt][2], c[mt][nt][3]);
                }
            }
            __syncthreads();
            const int d    = tid >> 1;
            const int half = tid & 1;
            const float* src = sVt + half * 64 * PT + d;
            uint16_t* dst = g_Vtb + (size_t)bh * Dq * Tq + (size_t)d * Tq + t0 + half * 64;
            #pragma unroll
            for (int blk = 0; blk < 4; ++blk) {
                #pragma unroll
                for (int q = 0; q < 4; ++q) {
                    const float v0 = src[(blk * 16 + 2 * q)     * PT];
                    const float v1 = src[(blk * 16 + 2 * q + 1) * PT];
                    const float v8 = src[(blk * 16 + 2 * q + 8) * PT];
                    const float v9 = src[(blk * 16 + 2 * q + 9) * PT];
                    *(uint2*)(dst + blk * 16 + 4 * q) = make_uint2(bf2(v0, v1), bf2(v8, v9));
                }
            }
        }
    }
}

// ============================================================================
// Kernel 2: mma.sync bf16 flash attention — 128-key super-tile edition.
//   Same proven 64-key sub-tile layout/body as R9; two sub-tiles per buffer,
//   2-buffer ping-pong, ONE CP_WAIT + __syncthreads per 128 keys (half the
//   barrier convoys). Staging issued after the barrier -> overlaps full tile.
// ============================================================================
#define QBLK 128
#define KBLK2 128                     // keys per super-tile
#define NT2  (Tq / KBLK2)             // 16 super-tiles
#define PKB  160                      // byte pitch of K/Vt smem rows
#define TILEB (64 * PKB)              // 10240 B per 64-key matrix sub-tile
#define SUPERB (4 * TILEB)            // K_A|Vt_A|K_B|Vt_B = 40960 B
#define SM_BYTES (2 * SUPERB)         // 2 ping-pong buffers = 81920 B

__global__ void __launch_bounds__(128, 2) attn_kernel(float* __restrict__ out)
{
    extern __shared__ __align__(16) char smc[];

    const int tid  = threadIdx.x;
    const int lane = tid & 31;
    const int wid  = tid >> 5;
    const int lg   = lane >> 2;
    const int lt   = lane & 3;

    const int bh = blockIdx.y;
    const int b  = bh >> 4;
    const int h  = bh & 15;
    const int q0 = blockIdx.x * QBLK;
    const int wq = q0 + wid * 32;

    const uint32_t smb = smem_u32(smc);
    const uint16_t* gKb  = g_Kb  + (size_t)bh * Tq * Dq;
    const uint16_t* gVtb = g_Vtb + (size_t)bh * Dq * Tq;

    // ---- Q fragments ----
    uint32_t aQ[2][4][4];
    {
        const uint16_t* Qb = g_Qb + ((size_t)bh * Tq + wq) * Dq;
        #pragma unroll
        for (int mt = 0; mt < 2; ++mt) {
            #pragma unroll
            for (int kj = 0; kj < 4; ++kj) {
                const uint2 lo = *(const uint2*)(Qb + (size_t)(mt * 16 + lg) * Dq + kj * 16 + 4 * lt);
                const uint2 hi = *(const uint2*)(Qb + (size_t)(mt * 16 + lg + 8) * Dq + kj * 16 + 4 * lt);
                aQ[mt][kj][0] = lo.x;
                aQ[mt][kj][1] = hi.x;
                aQ[mt][kj][2] = lo.y;
                aQ[mt][kj][3] = hi.y;
            }
        }
    }

    float o[2][8][4];
    #pragma unroll
    for (int mt = 0; mt < 2; ++mt)
        #pragma unroll
        for (int nt = 0; nt < 8; ++nt)
            #pragma unroll
            for (int e = 0; e < 4; ++e) o[mt][nt][e] = 0.f;

    float rs[4] = {0.f, 0.f, 0.f, 0.f};

    // ---- stage one 128-key super-tile (two 64-key sub-tiles) ----
    auto stage = [&](int it2, int buf) {
        const uint32_t base = smb + (uint32_t)(buf * SUPERB);
        #pragma unroll
        for (int hh = 0; hh < 2; ++hh) {
            const int s0 = it2 * KBLK2 + hh * 64;
            const uint32_t sKu  = base + (uint32_t)(hh * 2 * TILEB);
            const uint32_t sVtu = sKu + (uint32_t)TILEB;
            const uint16_t* gk = gKb + (size_t)s0 * Dq;
            #pragma unroll
            for (int j = 0; j < 4; ++j) {
                const int f = tid + 128 * j;
                const int r = f >> 3, i = f & 7;
                CP_ASYNC16(sKu + (uint32_t)(r * PKB + 16 * i), gk + (size_t)r * Dq + 8 * i);
                CP_ASYNC16(sVtu + (uint32_t)(r * PKB + 16 * i), gVtb + (size_t)r * Tq + s0 + 8 * i);
            }
        }
    };

    stage(0, 0);
    CP_COMMIT();

    int buf = 0;
    #pragma unroll 1
    for (int it2 = 0; it2 < NT2; ++it2) {
        CP_WAIT(0);          // super-tile it2 fully staged
        __syncthreads();     // visible to all; all warps done with it2-1's buffer
        if (it2 + 1 < NT2) {
            stage(it2 + 1, buf ^ 1);   // overlaps this tile's compute
            CP_COMMIT();
        }
        const char* sbase = smc + buf * SUPERB;
        buf ^= 1;

        // ---- two 64-key sub-tiles, proven R9 body each ----
        #pragma unroll
        for (int hh = 0; hh < 2; ++hh) {
            const char* sK  = sbase + hh * 2 * TILEB;
            const char* sVt = sK + TILEB;

            // ---- QK^T ----
            float c[2][8][4];
            #pragma unroll
            for (int mt = 0; mt < 2; ++mt)
                #pragma unroll
                for (int nt = 0; nt < 8; ++nt)
                    #pragma unroll
                    for (int e = 0; e < 4; ++e) c[mt][nt][e] = 0.f;

            #pragma unroll
            for (int kj = 0; kj < 4; ++kj) {
                #pragma unroll
                for (int nt = 0; nt < 8; ++nt) {
                    const uint2 bv = *(const uint2*)(sK + (nt * 8 + lg) * PKB + 32 * kj + 8 * lt);
                    mma_bf16(c[0][nt], aQ[0][kj], bv.x, bv.y);
                    mma_bf16(c[1][nt], aQ[1][kj], bv.x, bv.y);
                }
            }

            // ---- exp (pipelined into PV) + PV ----
            #define EXPP(jj) do { \
                _Pragma("unroll") \
                for (int mt = 0; mt < 2; ++mt) { \
                    _Pragma("unroll") \
                    for (int hh2 = 0; hh2 < 2; ++hh2) { \
                        float* cc = c[mt][2 * (jj) + hh2]; \
                        float p0 = ex2f(cc[0]); \
                        float p1 = ex2f(cc[1]); \
                        float p2 = ex2f(cc[2]); \
                        float p3 = ex2f(cc[3]); \
                        rs[mt * 2 + 0] += p0 + p1; \
                        rs[mt * 2 + 1] += p2 + p3; \
                        cc[0] = p0; cc[1] = p1; cc[2] = p2; cc[3] = p3; \
                    } \
                } \
            } while (0)

            EXPP(0);
            #pragma unroll
            for (int j = 0; j < 4; ++j) {
                if (j < 3) EXPP(j + 1);
                uint32_t aP0[4], aP1[4];
                aP0[0] = bf2(c[0][2*j][0],   c[0][2*j][1]);
                aP0[1] = bf2(c[0][2*j][2],   c[0][2*j][3]);
                aP0[2] = bf2(c[0][2*j+1][0], c[0][2*j+1][1]);
                aP0[3] = bf2(c[0][2*j+1][2], c[0][2*j+1][3]);
                aP1[0] = bf2(c[1][2*j][0],   c[1][2*j][1]);
                aP1[1] = bf2(c[1][2*j][2],   c[1][2*j][3]);
                aP1[2] = bf2(c[1][2*j+1][0], c[1][2*j+1][1]);
                aP1[3] = bf2(c[1][2*j+1][2], c[1][2*j+1][3]);
                #pragma unroll
                for (int nt = 0; nt < 8; ++nt) {
                    const uint2 bv = *(const uint2*)(sVt + (nt * 8 + lg) * PKB + 32 * j + 8 * lt);
                    mma_bf16(o[0][nt], aP0, bv.x, bv.y);
                    mma_bf16(o[1][nt], aP1, bv.x, bv.y);
                }
            }
            #undef EXPP
        }
    }

    // ---- row sums ----
    float inv[4];
    #pragma unroll
    for (int i = 0; i < 4; ++i) {
        float v = rs[i];
        v += __shfl_xor_sync(0xffffffffu, v, 1);
        v += __shfl_xor_sync(0xffffffffu, v, 2);
        inv[i] = 1.f / v;
    }

    // ---- epilogue: O/l + V residual (fp32) -> out[b, t, h*64 + d] ----
    #pragma unroll
    for (int mt = 0; mt < 2; ++mt) {
        #pragma unroll
        for (int half = 0; half < 2; ++half) {
            const int t  = wq + mt * 16 + half * 8 + lg;
            const float iv = inv[mt * 2 + half];
            const float2* vr = (const float2*)(g_V + ((size_t)bh * Tq + t) * Dq);
            float2* op = (float2*)(out + ((size_t)(b * Tq + t)) * Eq + h * Dq);
            #pragma unroll
            for (int nt = 0; nt < 8; ++nt) {
                const int idx = nt * 4 + lt;
                float2 v = vr[idx];
                op[idx] = make_float2(o[mt][nt][half * 2 + 0] * iv + v.x,
                                      o[mt][nt][half * 2 + 1] * iv + v.y);
            }
        }
    }
}

// ============================================================================
extern "C" void kernel_launch(void* const* d_in, const int* in_sizes, int n_in,
                              void* d_out, int out_size)
{
    const float* x  = (const float*)d_in[0];
    const float* Wq = (const float*)d_in[1];
    const float* Wk = (const float*)d_in[2];
    const float* Wv = (const float*)d_in[3];
    float* out = (float*)d_out;

    cudaFuncSetAttribute(attn_kernel, cudaFuncAttributeMaxDynamicSharedMemorySize, SM_BYTES);

    dim3 pgrid(Tq / 128, BHq);
    proj_kernel<<<pgrid, 128>>>(x, Wq, Wk, Wv);

    dim3 agrid(Tq / QBLK, BHq);
    attn_kernel<<<agrid, 128, SM_BYTES>>>(out);
}

// round 17
// speedup vs baseline: 1.0328x; 1.0328x over previous
#include <cuda_runtime.h>
#include <math.h>
#include <stdint.h>

// Problem constants
#define Bq   4
#define Tq   2048
#define Eq   1024
#define Hq   16
#define Dq   64
#define BHq  (Bq*Hq)

// Scratch (alloc-free rule: static __device__ arrays).
__device__ uint16_t g_Qb [(size_t)BHq * Tq * Dq];  // bf16, d pair-permuted, pre-scaled
__device__ uint16_t g_Kb [(size_t)BHq * Tq * Dq];  // bf16, d pair-permuted
__device__ float    g_V  [(size_t)BHq * Tq * Dq];  // fp32 row-major (exact residual)
__device__ uint16_t g_Vtb[(size_t)BHq * Dq * Tq];  // bf16, transposed, t pair-permuted

#define SCALE_LOG2E 0.18033688011112042f   // 0.125 * log2(e)

// ---- bf16 pack: {lo, hi} -> bf16x2 in one u32 ----
__device__ __forceinline__ uint32_t bf2(float lo, float hi) {
    uint32_t r;
    asm("cvt.rn.bf16x2.f32 %0, %1, %2;" : "=r"(r) : "f"(hi), "f"(lo));
    return r;
}

// split a float2 into bf16x2 hi part and bf16x2 residual (lo) part.
__device__ __forceinline__ void split2(float2 p, uint32_t& hi, uint32_t& lo) {
    hi = bf2(p.x, p.y);
    float h0 = __uint_as_float(hi << 16);
    float h1 = __uint_as_float(hi & 0xffff0000u);
    lo = bf2(p.x - h0, p.y - h1);
}

// ---- warp-level bf16 MMA: D(16x8,f32) += A(16x16,bf16) * B(16x8,bf16) ----
__device__ __forceinline__ void mma_bf16(float c[4], const uint32_t a[4],
                                         uint32_t b0, uint32_t b1) {
    asm volatile(
        "mma.sync.aligned.m16n8k16.row.col.f32.bf16.bf16.f32 "
        "{%0,%1,%2,%3}, {%4,%5,%6,%7}, {%8,%9}, {%0,%1,%2,%3};"
        : "+f"(c[0]), "+f"(c[1]), "+f"(c[2]), "+f"(c[3])
        : "r"(a[0]), "r"(a[1]), "r"(a[2]), "r"(a[3]), "r"(b0), "r"(b1));
}

__device__ __forceinline__ float ex2f(float x) {
    float r; asm("ex2.approx.f32 %0, %1;" : "=f"(r) : "f"(x)); return r;
}
__device__ __forceinline__ uint32_t smem_u32(const void* p) {
    uint32_t a;
    asm("{ .reg .u64 t; cvta.to.shared.u64 t, %1; cvt.u32.u64 %0, t; }" : "=r"(a) : "l"(p));
    return a;
}

#define CP_ASYNC16(dst_u32, src_ptr) \
    asm volatile("cp.async.ca.shared.global [%0], [%1], 16;" :: "r"(dst_u32), "l"(src_ptr) : "memory")
#define CP_COMMIT() asm volatile("cp.async.commit_group;" ::: "memory")
#define CP_WAIT(n)  asm volatile("cp.async.wait_group %0;" :: "n"(n) : "memory")

// ============================================================================
// Kernel 1: tensor-core projections, error-compensated bf16 (R9 body) with
//   COALESCED Q/K epilogues via smem bounce. PQK=72 (144B pitch, 16B-aligned
//   — R16's 68 was misaligned for uint4 and crashed).
// ============================================================================
#define PT   66    // sVt transpose pitch (floats)
#define PQK  72    // Q/K smem bounce pitch (uint16): 144 B, 16B-aligned

__global__ void __launch_bounds__(128) proj_kernel(
    const float* __restrict__ x,
    const float* __restrict__ Wq,
    const float* __restrict__ Wk,
    const float* __restrict__ Wv)
{
    __shared__ __align__(16) float sVt[128 * PT];         // 33792 B (reused as sQK)
    uint16_t* sQK = (uint16_t*)sVt;                       // 128 * 72 * 2 = 18432 B

    const int tid  = threadIdx.x;
    const int lane = tid & 31;
    const int wid  = tid >> 5;
    const int lg   = lane >> 2;
    const int lt   = lane & 3;

    const int bh = blockIdx.y;
    const int b  = bh >> 4;
    const int h  = bh & 15;
    const int t0 = blockIdx.x * 128;
    const int wq = t0 + wid * 32;

    // ---- load x tile as hi/lo bf16 A-fragments ----
    uint32_t aXh[2][4][4], aXl[2][4][4];
    #pragma unroll
    for (int mt = 0; mt < 2; ++mt) {
        #pragma unroll
        for (int kj = 0; kj < 4; ++kj) {
            const int r0 = wq + mt * 16 + lg;
            const float* p = x + ((size_t)(b * Tq + r0)) * Eq + h * Dq + kj * 16 + 2 * lt;
            float2 lo0 = *(const float2*)(p);
            float2 hi0 = *(const float2*)(p + 8);
            const float* q = p + (size_t)8 * Eq;
            float2 lo1 = *(const float2*)(q);
            float2 hi1 = *(const float2*)(q + 8);
            split2(lo0, aXh[mt][kj][0], aXl[mt][kj][0]);
            split2(lo1, aXh[mt][kj][1], aXl[mt][kj][1]);
            split2(hi0, aXh[mt][kj][2], aXl[mt][kj][2]);
            split2(hi1, aXh[mt][kj][3], aXl[mt][kj][3]);
        }
    }

    #pragma unroll 1
    for (int m = 0; m < 3; ++m) {
        const float* W = (m == 0) ? Wq : ((m == 1) ? Wk : Wv);

        float c[2][8][4];
        #pragma unroll
        for (int mt = 0; mt < 2; ++mt)
            #pragma unroll
            for (int nt = 0; nt < 8; ++nt)
                #pragma unroll
                for (int e = 0; e < 4; ++e) c[mt][nt][e] = 0.f;

        #pragma unroll
        for (int kj = 0; kj < 4; ++kj) {
            #pragma unroll
            for (int nt = 0; nt < 8; ++nt) {
                const float* wp = W + (size_t)(nt * 8 + lg) * 64 + kj * 16 + 2 * lt;
                uint32_t wh0, wl0, wh1, wl1;
                split2(*(const float2*)(wp),     wh0, wl0);
                split2(*(const float2*)(wp + 8), wh1, wl1);
                #pragma unroll
                for (int mt = 0; mt < 2; ++mt) {
                    mma_bf16(c[mt][nt], aXh[mt][kj], wh0, wh1);
                    mma_bf16(c[mt][nt], aXl[mt][kj], wh0, wh1);
                    mma_bf16(c[mt][nt], aXh[mt][kj], wl0, wl1);
                }
            }
        }

        if (m < 2) {
            // ---- Q/K epilogue: smem bounce, then coalesced 16B-chunk STG ----
            __syncthreads();   // previous use of the smem buffer complete
            const float s = (m == 0) ? SCALE_LOG2E : 1.0f;
            #pragma unroll
            for (int mt = 0; mt < 2; ++mt) {
                const int row0 = wid * 32 + mt * 16 + lg;     // local t
                #pragma unroll
                for (int nt = 0; nt < 8; ++nt) {
                    const int pos = 16 * (nt >> 1) + 4 * lt + 2 * (nt & 1);
                    *(uint32_t*)(sQK + row0 * PQK + pos) =
                        bf2(c[mt][nt][0] * s, c[mt][nt][1] * s);
                    *(uint32_t*)(sQK + (row0 + 8) * PQK + pos) =
                        bf2(c[mt][nt][2] * s, c[mt][nt][3] * s);
                }
            }
            __syncthreads();
            // stream out: chunk f covers row f>>3, 16B chunk (f&7); 8 lanes/row
            uint16_t* g = ((m == 0) ? g_Qb : g_Kb) + ((size_t)bh * Tq + t0) * Dq;
            #pragma unroll
            for (int j = 0; j < 8; ++j) {
                const int f = tid + 128 * j;
                const int r = f >> 3, i = f & 7;
                *(uint4*)(g + (size_t)r * Dq + 8 * i) =
                    *(const uint4*)(sQK + r * PQK + 8 * i);
            }
            __syncthreads();   // buffer free before next m reuses it
        } else {
            // ---- V epilogue: fp32 row-major + smem stage for transpose ----
            #pragma unroll
            for (int mt = 0; mt < 2; ++mt) {
                const int t    = wq + mt * 16 + lg;
                const int tloc = wid * 32 + mt * 16 + lg;
                float* r0 = g_V + ((size_t)bh * Tq + t) * Dq;
                float* r1 = r0 + (size_t)8 * Dq;
                #pragma unroll
                for (int nt = 0; nt < 8; ++nt) {
                    const int col = nt * 8 + 2 * lt;
                    *(float2*)(r0 + col) = make_float2(c[mt][nt][0], c[mt][nt][1]);
                    *(float2*)(r1 + col) = make_float2(c[mt][nt][2], c[mt][nt][3]);
                    *(float2*)(sVt + tloc * PT + col)       = make_float2(c[mt][nt][0], c[mt][nt][1]);
                    *(float2*)(sVt + (tloc + 8) * PT + col) = make_float2(c[mt][nt][2], c[mt][nt][3]);
                }
            }
            __syncthreads();
            const int d    = tid >> 1;
            const int half = tid & 1;
            const float* src = sVt + half * 64 * PT + d;
            uint16_t* dst = g_Vtb + (size_t)bh * Dq * Tq + (size_t)d * Tq + t0 + half * 64;
            #pragma unroll
            for (int blk = 0; blk < 4; ++blk) {
                #pragma unroll
                for (int q = 0; q < 4; ++q) {
                    const float v0 = src[(blk * 16 + 2 * q)     * PT];
                    const float v1 = src[(blk * 16 + 2 * q + 1) * PT];
                    const float v8 = src[(blk * 16 + 2 * q + 8) * PT];
                    const float v9 = src[(blk * 16 + 2 * q + 9) * PT];
                    *(uint2*)(dst + blk * 16 + 4 * q) = make_uint2(bf2(v0, v1), bf2(v8, v9));
                }
            }
        }
    }
}

// ============================================================================
// Kernel 2: mma.sync bf16 flash attention (R9/R14 — proven 186us, UNCHANGED).
// ============================================================================
#define QBLK 128
#define KBLK 64
#define NT   (Tq / KBLK)              // 32 tiles
#define PKB  160                      // byte pitch of K/Vt smem rows
#define TILEB (64 * PKB)              // 10240 B per tile
#define SM_BYTES (8 * TILEB)          // 4 bufs x (K + Vt) = 81920 B

__global__ void __launch_bounds__(128, 2) attn_kernel(float* __restrict__ out)
{
    extern __shared__ __align__(16) char smc[];

    const int tid  = threadIdx.x;
    const int lane = tid & 31;
    const int wid  = tid >> 5;
    const int lg   = lane >> 2;
    const int lt   = lane & 3;

    const int bh = blockIdx.y;
    const int b  = bh >> 4;
    const int h  = bh & 15;
    const int q0 = blockIdx.x * QBLK;
    const int wq = q0 + wid * 32;

    const uint32_t smb = smem_u32(smc);
    const uint16_t* gKb  = g_Kb  + (size_t)bh * Tq * Dq;
    const uint16_t* gVtb = g_Vtb + (size_t)bh * Dq * Tq;

    // ---- Q fragments: m16n8k16 A-frags ----
    uint32_t aQ[2][4][4];
    {
        const uint16_t* Qb = g_Qb + ((size_t)bh * Tq + wq) * Dq;
        #pragma unroll
        for (int mt = 0; mt < 2; ++mt) {
            #pragma unroll
            for (int kj = 0; kj < 4; ++kj) {
                const uint2 lo = *(const uint2*)(Qb + (size_t)(mt * 16 + lg) * Dq + kj * 16 + 4 * lt);
                const uint2 hi = *(const uint2*)(Qb + (size_t)(mt * 16 + lg + 8) * Dq + kj * 16 + 4 * lt);
                aQ[mt][kj][0] = lo.x;
                aQ[mt][kj][1] = hi.x;
                aQ[mt][kj][2] = lo.y;
                aQ[mt][kj][3] = hi.y;
            }
        }
    }

    float o[2][8][4];
    #pragma unroll
    for (int mt = 0; mt < 2; ++mt)
        #pragma unroll
        for (int nt = 0; nt < 8; ++nt)
            #pragma unroll
            for (int e = 0; e < 4; ++e) o[mt][nt][e] = 0.f;

    float rs[4] = {0.f, 0.f, 0.f, 0.f};

    auto stage = [&](int it, int buf) {
        const uint32_t sKu  = smb + (uint32_t)(buf * 2 * TILEB);
        const uint32_t sVtu = sKu + (uint32_t)TILEB;
        const uint16_t* gk = gKb + (size_t)it * KBLK * Dq;
        const int s0 = it * KBLK;
        #pragma unroll
        for (int j = 0; j < 4; ++j) {
            const int f = tid + 128 * j;
            const int r = f >> 3, i = f & 7;
            CP_ASYNC16(sKu + (uint32_t)(r * PKB + 16 * i), gk + (size_t)r * Dq + 8 * i);
            CP_ASYNC16(sVtu + (uint32_t)(r * PKB + 16 * i), gVtb + (size_t)r * Tq + s0 + 8 * i);
        }
    };

    stage(0, 0); CP_COMMIT();
    stage(1, 1); CP_COMMIT();

    #pragma unroll 1
    for (int it = 0; it < NT; ++it) {
        if (it + 2 < NT) {
            stage(it + 2, (it + 2) & 3);
            CP_COMMIT();
            CP_WAIT(2);
        } else if (it + 1 < NT) {
            CP_WAIT(1);
        } else {
            CP_WAIT(0);
        }
        __syncthreads();

        const char* sK  = smc + (it & 3) * 2 * TILEB;
        const char* sVt = sK + TILEB;

        // ---- QK^T ----
        float c[2][8][4];
        #pragma unroll
        for (int mt = 0; mt < 2; ++mt)
            #pragma unroll
            for (int nt = 0; nt < 8; ++nt)
                #pragma unroll
                for (int e = 0; e < 4; ++e) c[mt][nt][e] = 0.f;

        #pragma unroll
        for (int kj = 0; kj < 4; ++kj) {
            #pragma unroll
            for (int nt = 0; nt < 8; ++nt) {
                const uint2 bv = *(const uint2*)(sK + (nt * 8 + lg) * PKB + 32 * kj + 8 * lt);
                mma_bf16(c[0][nt], aQ[0][kj], bv.x, bv.y);
                mma_bf16(c[1][nt], aQ[1][kj], bv.x, bv.y);
            }
        }

        // ---- exp (pipelined into PV) + PV ----
        #define EXPP(jj) do { \
            _Pragma("unroll") \
            for (int mt = 0; mt < 2; ++mt) { \
                _Pragma("unroll") \
                for (int hh = 0; hh < 2; ++hh) { \
                    float* cc = c[mt][2 * (jj) + hh]; \
                    float p0 = ex2f(cc[0]); \
                    float p1 = ex2f(cc[1]); \
                    float p2 = ex2f(cc[2]); \
                    float p3 = ex2f(cc[3]); \
                    rs[mt * 2 + 0] += p0 + p1; \
                    rs[mt * 2 + 1] += p2 + p3; \
                    cc[0] = p0; cc[1] = p1; cc[2] = p2; cc[3] = p3; \
                } \
            } \
        } while (0)

        EXPP(0);
        #pragma unroll
        for (int j = 0; j < 4; ++j) {
            if (j < 3) EXPP(j + 1);
            uint32_t aP0[4], aP1[4];
            aP0[0] = bf2(c[0][2*j][0],   c[0][2*j][1]);
            aP0[1] = bf2(c[0][2*j][2],   c[0][2*j][3]);
            aP0[2] = bf2(c[0][2*j+1][0], c[0][2*j+1][1]);
            aP0[3] = bf2(c[0][2*j+1][2], c[0][2*j+1][3]);
            aP1[0] = bf2(c[1][2*j][0],   c[1][2*j][1]);
            aP1[1] = bf2(c[1][2*j][2],   c[1][2*j][3]);
            aP1[2] = bf2(c[1][2*j+1][0], c[1][2*j+1][1]);
            aP1[3] = bf2(c[1][2*j+1][2], c[1][2*j+1][3]);
            #pragma unroll
            for (int nt = 0; nt < 8; ++nt) {
                const uint2 bv = *(const uint2*)(sVt + (nt * 8 + lg) * PKB + 32 * j + 8 * lt);
                mma_bf16(o[0][nt], aP0, bv.x, bv.y);
                mma_bf16(o[1][nt], aP1, bv.x, bv.y);
            }
        }
        #undef EXPP
    }

    // ---- row sums ----
    float inv[4];
    #pragma unroll
    for (int i = 0; i < 4; ++i) {
        float v = rs[i];
        v += __shfl_xor_sync(0xffffffffu, v, 1);
        v += __shfl_xor_sync(0xffffffffu, v, 2);
        inv[i] = 1.f / v;
    }

    // ---- epilogue: O/l + V residual (fp32) -> out[b, t, h*64 + d] ----
    #pragma unroll
    for (int mt = 0; mt < 2; ++mt) {
        #pragma unroll
        for (int half = 0; half < 2; ++half) {
            const int t  = wq + mt * 16 + half * 8 + lg;
            const float iv = inv[mt * 2 + half];
            const float2* vr = (const float2*)(g_V + ((size_t)bh * Tq + t) * Dq);
            float2* op = (float2*)(out + ((size_t)(b * Tq + t)) * Eq + h * Dq);
            #pragma unroll
            for (int nt = 0; nt < 8; ++nt) {
                const int idx = nt * 4 + lt;
                float2 v = vr[idx];
                op[idx] = make_float2(o[mt][nt][half * 2 + 0] * iv + v.x,
                                      o[mt][nt][half * 2 + 1] * iv + v.y);
            }
        }
    }
}

// ============================================================================
extern "C" void kernel_launch(void* const* d_in, const int* in_sizes, int n_in,
                              void* d_out, int out_size)
{
    const float* x  = (const float*)d_in[0];
    const float* Wq = (const float*)d_in[1];
    const float* Wk = (const float*)d_in[2];
    const float* Wv = (const float*)d_in[3];
    float* out = (float*)d_out;

    cudaFuncSetAttribute(attn_kernel, cudaFuncAttributeMaxDynamicSharedMemorySize, SM_BYTES);

    dim3 pgrid(Tq / 128, BHq);
    proj_kernel<<<pgrid, 128>>>(x, Wq, Wk, Wv);

    dim3 agrid(Tq / QBLK, BHq);
    attn_kernel<<<agrid, 128, SM_BYTES>>>(out);
}